// round 1
// baseline (speedup 1.0000x reference)
#include <cuda_runtime.h>
#include <cstdint>

#define NN 100000
#define NE 1600000
#define DD 128

// -------- scratch (device globals: no allocation allowed) --------
__device__ __align__(256) float g_agg[(size_t)NN * DD];   // 51.2 MB
__device__ __align__(256) float g_h[(size_t)NN * DD];     // 51.2 MB
__device__ __align__(256) float g_deg[NN];
__device__ int g_is64;

// -------- edge dtype detection: int64 -> odd 32-bit words are all 0 --------
__global__ void k_detect(const unsigned int* __restrict__ e) {
    int bad = 0;
    for (int i = threadIdx.x; i < 256; i += 32)
        if (e[2 * i + 1] != 0u) bad = 1;
    unsigned any = __ballot_sync(0xffffffffu, bad);
    if (threadIdx.x == 0) g_is64 = (any == 0u) ? 1 : 0;
}

// -------- zero agg (and deg) --------
__global__ void k_zero(int with_deg) {
    int stride = gridDim.x * blockDim.x;
    int i = blockIdx.x * blockDim.x + threadIdx.x;
    float4 z = make_float4(0.f, 0.f, 0.f, 0.f);
    const int n4 = NN * DD / 4;
    float4* a4 = reinterpret_cast<float4*>(g_agg);
    for (int idx = i; idx < n4; idx += stride) a4[idx] = z;
    if (with_deg) {
        float4* d4 = reinterpret_cast<float4*>(g_deg);
        for (int idx = i; idx < NN / 4; idx += stride) d4[idx] = z;
    }
}

// -------- scatter: one warp per edge, vector RED to L2 --------
__global__ void k_scatter(const float* __restrict__ xext,
                          const void* __restrict__ edge,
                          int with_deg, int use_h) {
    const float* __restrict__ src_feat = use_h ? g_h : xext;
    unsigned gw = (blockIdx.x * blockDim.x + threadIdx.x) >> 5;
    int lane = threadIdx.x & 31;
    if (gw >= NE) return;
    int s, d;
    if (g_is64) {
        const long long* e = (const long long*)edge;
        s = (int)e[gw];
        d = (int)e[NE + gw];
    } else {
        const int* e = (const int*)edge;
        s = e[gw];
        d = e[NE + gw];
    }
    float4 v = reinterpret_cast<const float4*>(src_feat + (size_t)s * DD)[lane];
    const float* dp = g_agg + (size_t)d * DD + lane * 4;
    unsigned long long ga;
    asm("cvta.to.global.u64 %0, %1;" : "=l"(ga) : "l"(dp));
    asm volatile("red.global.add.v4.f32 [%0], {%1,%2,%3,%4};"
                 :: "l"(ga), "f"(v.x), "f"(v.y), "f"(v.z), "f"(v.w)
                 : "memory");
    if (with_deg && lane == 0) atomicAdd(&g_deg[d], 1.0f);
}

// -------- fused SAGE layer GEMM --------
// out[row, col] = sum_k A[row,k] * W[col,k], K = 256:
//   A[:, 0:128]   = agg * (1/max(deg,1))   (mean-aggregated features)
//   A[:, 128:256] = x (or h)
//   W[:, 0:128]   = W_l ; W[:, 128:256] = W_r
// Inner product uses fma.rn.f32x2: even-k partials in lo lane, odd-k in hi lane.
#define TM 64
#define SP 258               // padded smem row stride (floats): 2-bank shift/row
#define SMEM_BYTES ((TM + 128) * SP * 4)

__global__ __launch_bounds__(256, 1)
void k_gemm(const float* __restrict__ Xext,
            const float* __restrict__ Wl, const float* __restrict__ Wr,
            const float* __restrict__ bias,
            float* __restrict__ outext,
            int use_h_in, int use_h_out, int do_relu) {
    extern __shared__ float sm[];
    float* As = sm;              // [64][258]
    float* Ws = sm + TM * SP;    // [128][258]
    const float* __restrict__ X = use_h_in ? g_h : Xext;
    float* __restrict__ out = use_h_out ? g_h : outext;

    int tid = threadIdx.x;
    int row0 = blockIdx.x * TM;

    // Load both weight matrices: 128 rows x (128+128) k
    for (int i = tid; i < 4096; i += 256) {           // 4096 float4 per matrix
        int o = i >> 5, k4 = (i & 31) * 4;
        float4 w0 = reinterpret_cast<const float4*>(Wl)[i];
        float4 w1 = reinterpret_cast<const float4*>(Wr)[i];
        float* p0 = Ws + o * SP + k4;
        p0[0] = w0.x; p0[1] = w0.y; p0[2] = w0.z; p0[3] = w0.w;
        float* p1 = Ws + o * SP + 128 + k4;
        p1[0] = w1.x; p1[1] = w1.y; p1[2] = w1.z; p1[3] = w1.w;
    }
    // Load A tile: mean part (scaled agg) + x part
    for (int i = tid; i < 2048; i += 256) {           // 64 rows x 32 float4
        int r = i >> 5, q = (i & 31);
        int row = row0 + r;
        float4 a = make_float4(0.f, 0.f, 0.f, 0.f);
        float4 xv = a;
        if (row < NN) {
            float inv = 1.0f / fmaxf(g_deg[row], 1.0f);
            float4 ag = reinterpret_cast<const float4*>(g_agg + (size_t)row * DD)[q];
            a.x = ag.x * inv; a.y = ag.y * inv; a.z = ag.z * inv; a.w = ag.w * inv;
            xv = reinterpret_cast<const float4*>(X + (size_t)row * DD)[q];
        }
        float* pa = As + r * SP + q * 4;
        pa[0] = a.x; pa[1] = a.y; pa[2] = a.z; pa[3] = a.w;
        float* px = As + r * SP + 128 + q * 4;
        px[0] = xv.x; px[1] = xv.y; px[2] = xv.z; px[3] = xv.w;
    }
    __syncthreads();

    int cg = tid & 15;           // col group: cols cg + 16*c, c=0..7
    int rg = tid >> 4;           // row group: rows rg*4 + r, r=0..3
    const float* Abase = As + (rg * 4) * SP;
    const float* Wbase = Ws + cg * SP;

    unsigned long long acc[4][8];
#pragma unroll
    for (int r = 0; r < 4; r++)
#pragma unroll
        for (int c = 0; c < 8; c++) acc[r][c] = 0ull;

#pragma unroll 2
    for (int kk = 0; kk < 128; kk++) {
        unsigned long long a[4], w[8];
#pragma unroll
        for (int r = 0; r < 4; r++)
            a[r] = *reinterpret_cast<const unsigned long long*>(Abase + r * SP + 2 * kk);
#pragma unroll
        for (int c = 0; c < 8; c++)
            w[c] = *reinterpret_cast<const unsigned long long*>(Wbase + c * 16 * SP + 2 * kk);
#pragma unroll
        for (int r = 0; r < 4; r++)
#pragma unroll
            for (int c = 0; c < 8; c++)
                asm("fma.rn.f32x2 %0, %1, %2, %0;"
                    : "+l"(acc[r][c]) : "l"(a[r]), "l"(w[c]));
    }

#pragma unroll
    for (int r = 0; r < 4; r++) {
        int row = row0 + rg * 4 + r;
        if (row < NN) {
#pragma unroll
            for (int c = 0; c < 8; c++) {
                int col = cg + 16 * c;
                float lo = __uint_as_float((unsigned)(acc[r][c] & 0xffffffffull));
                float hi = __uint_as_float((unsigned)(acc[r][c] >> 32));
                float v = lo + hi + bias[col];
                if (do_relu) v = fmaxf(v, 0.f);
                out[(size_t)row * DD + col] = v;
            }
        }
    }
}

extern "C" void kernel_launch(void* const* d_in, const int* in_sizes, int n_in,
                              void* d_out, int out_size) {
    const float* x   = (const float*)d_in[0];
    const void*  edg = d_in[1];
    const float* W1l = (const float*)d_in[2];
    const float* b1  = (const float*)d_in[3];
    const float* W1r = (const float*)d_in[4];
    const float* W2l = (const float*)d_in[5];
    const float* b2  = (const float*)d_in[6];
    const float* W2r = (const float*)d_in[7];
    float* out = (float*)d_out;

    cudaFuncSetAttribute(k_gemm, cudaFuncAttributeMaxDynamicSharedMemorySize, SMEM_BYTES);

    const int gemm_blocks = (NN + TM - 1) / TM;      // 1563
    const int scat_blocks = NE / 8;                   // warp per edge, 256 thr/blk

    k_detect<<<1, 32>>>((const unsigned int*)edg);

    // Layer 1
    k_zero<<<2048, 256>>>(1);
    k_scatter<<<scat_blocks, 256>>>(x, edg, /*with_deg=*/1, /*use_h=*/0);
    k_gemm<<<gemm_blocks, 256, SMEM_BYTES>>>(x, W1l, W1r, b1, out,
                                             /*use_h_in=*/0, /*use_h_out=*/1, /*relu=*/1);
    // Layer 2
    k_zero<<<2048, 256>>>(0);
    k_scatter<<<scat_blocks, 256>>>(x, edg, /*with_deg=*/0, /*use_h=*/1);
    k_gemm<<<gemm_blocks, 256, SMEM_BYTES>>>(x, W2l, W2r, b2, out,
                                             /*use_h_in=*/1, /*use_h_out=*/0, /*relu=*/0);
}

// round 2
// speedup vs baseline: 1.1065x; 1.1065x over previous
#include <cuda_runtime.h>
#include <cstdint>
typedef unsigned long long ull;

#define NN 100000
#define NE 1600000
#define DD 128

// -------- scratch (device globals: no allocation allowed) --------
__device__ __align__(256) float g_agg[(size_t)NN * DD];   // 51.2 MB
__device__ __align__(256) float g_h[(size_t)NN * DD];     // 51.2 MB
__device__ __align__(256) float g_deg[NN];
__device__ int g_is64;

// -------- edge dtype detection: int64 -> odd 32-bit words are all 0 --------
__global__ void k_detect(const unsigned int* __restrict__ e) {
    int bad = 0;
    for (int i = threadIdx.x; i < 256; i += 32)
        if (e[2 * i + 1] != 0u) bad = 1;
    unsigned any = __ballot_sync(0xffffffffu, bad);
    if (threadIdx.x == 0) g_is64 = (any == 0u) ? 1 : 0;
}

// -------- zero agg (and deg) --------
__global__ void k_zero(int with_deg) {
    int stride = gridDim.x * blockDim.x;
    int i = blockIdx.x * blockDim.x + threadIdx.x;
    float4 z = make_float4(0.f, 0.f, 0.f, 0.f);
    const int n4 = NN * DD / 4;
    float4* a4 = reinterpret_cast<float4*>(g_agg);
    for (int idx = i; idx < n4; idx += stride) a4[idx] = z;
    if (with_deg) {
        float4* d4 = reinterpret_cast<float4*>(g_deg);
        for (int idx = i; idx < NN / 4; idx += stride) d4[idx] = z;
    }
}

// -------- scatter: one warp per edge, vector RED to L2 --------
__global__ void k_scatter(const float* __restrict__ xext,
                          const void* __restrict__ edge,
                          int with_deg, int use_h) {
    const float* __restrict__ src_feat = use_h ? g_h : xext;
    unsigned gw = (blockIdx.x * blockDim.x + threadIdx.x) >> 5;
    int lane = threadIdx.x & 31;
    if (gw >= NE) return;
    int s, d;
    if (g_is64) {
        const long long* e = (const long long*)edge;
        s = (int)e[gw];
        d = (int)e[NE + gw];
    } else {
        const int* e = (const int*)edge;
        s = e[gw];
        d = e[NE + gw];
    }
    float4 v = reinterpret_cast<const float4*>(src_feat + (size_t)s * DD)[lane];
    const float* dp = g_agg + (size_t)d * DD + lane * 4;
    unsigned long long ga;
    asm("cvta.to.global.u64 %0, %1;" : "=l"(ga) : "l"(dp));
    asm volatile("red.global.add.v4.f32 [%0], {%1,%2,%3,%4};"
                 :: "l"(ga), "f"(v.x), "f"(v.y), "f"(v.z), "f"(v.w)
                 : "memory");
    if (with_deg && lane == 0) atomicAdd(&g_deg[d], 1.0f);
}

// -------- scale agg by 1/max(deg,1) in place (hoisted out of GEMM) --------
__global__ void k_mean() {
    int stride = gridDim.x * blockDim.x;
    const int n4 = NN * DD / 4;
    float4* a4 = reinterpret_cast<float4*>(g_agg);
    for (int idx = blockIdx.x * blockDim.x + threadIdx.x; idx < n4; idx += stride) {
        int node = idx >> 5;                       // 32 float4 per node
        float inv = 1.0f / fmaxf(g_deg[node], 1.0f);
        float4 v = a4[idx];
        v.x *= inv; v.y *= inv; v.z *= inv; v.w *= inv;
        a4[idx] = v;
    }
}

// -------- fused SAGE layer GEMM --------
// out[row, col] = sum_{k<256} A[row,k] * W[col,k]
//   A[:,0:128] = g_agg (already mean-scaled), A[:,128:256] = X
//   W[:,0:128] = W_l,  W[:,128:256] = W_r
// 128x128 block tile, 256 threads, 8x8 f32x2 outputs per thread.
// W resident in smem pair-transposed [kp][col]; A double-buffered in 64-k chunks.
#define AS_STRIDE 68                       // floats per A smem row (16B aligned, bank-spread)
#define AS_SZ (128 * AS_STRIDE)            // floats per A buffer
#define WP_STRIDE 130                      // ull per W smem kp-row (pad vs STS conflicts)
#define GSMEM (2 * AS_SZ * 4 + 128 * WP_STRIDE * 8)   // 69632 + 133120 = 202752 B

__global__ __launch_bounds__(256, 1)
void k_gemm(const float* __restrict__ Xext,
            const float* __restrict__ Wl, const float* __restrict__ Wr,
            const float* __restrict__ bias,
            float* __restrict__ outext,
            int use_h_in, int use_h_out, int do_relu) {
    extern __shared__ float sm[];
    float* As = sm;                                  // [2][128][68]
    ull* Wp = reinterpret_cast<ull*>(sm + 2 * AS_SZ); // [128 kp][130]
    const float* __restrict__ X = use_h_in ? g_h : Xext;
    float* __restrict__ out = use_h_out ? g_h : outext;

    int tid = threadIdx.x;
    int row0 = blockIdx.x * 128;
    int wid = tid >> 5, lane = tid & 31;
    int wr = wid & 3, wc = wid >> 2;       // warp tile: 4 x 2 of 32x64
    int lr = lane >> 3, lc = lane & 7;     // lane tile: 4 x 8

    // ---- load both W matrices, pair-transposed: Wp[kp][col] = (W[col,2kp],W[col,2kp+1])
    {
        const float2* w0 = (const float2*)Wl;
        const float2* w1 = (const float2*)Wr;
        for (int i = tid; i < 8192; i += 256) {      // 128 cols x 64 kp per matrix
            int col = i >> 6, kpl = i & 63;
            float2 v0 = w0[col * 64 + kpl];
            float2 v1 = w1[col * 64 + kpl];
            Wp[kpl * WP_STRIDE + col] = *reinterpret_cast<ull*>(&v0);
            Wp[(kpl + 64) * WP_STRIDE + col] = *reinterpret_cast<ull*>(&v1);
        }
    }

    float4 ld[8];
    // chunk c covers k in [c*64, c*64+64): c<2 -> g_agg (mean), else X
    auto load_chunk = [&](int c) {
        const float* P = (c < 2) ? g_agg : X;
        int off = (c & 1) * 64;
#pragma unroll
        for (int j = 0; j < 8; j++) {
            int i = j * 256 + tid;
            int r = i >> 4, f4c = i & 15;
            int row = row0 + r;
            if (row < NN)
                ld[j] = *reinterpret_cast<const float4*>(P + (size_t)row * DD + off + f4c * 4);
            else
                ld[j] = make_float4(0.f, 0.f, 0.f, 0.f);
        }
    };
    auto store_chunk = [&](int b) {
#pragma unroll
        for (int j = 0; j < 8; j++) {
            int i = j * 256 + tid;
            int r = i >> 4, f4c = i & 15;
            *reinterpret_cast<float4*>(As + b * AS_SZ + r * AS_STRIDE + f4c * 4) = ld[j];
        }
    };

    ull acc[8][8];
#pragma unroll
    for (int r = 0; r < 8; r++)
#pragma unroll
        for (int c = 0; c < 8; c++) acc[r][c] = 0ull;

    load_chunk(0);
    store_chunk(0);
    __syncthreads();

    for (int c = 0; c < 4; c++) {
        if (c < 3) load_chunk(c + 1);                // issue next-chunk LDGs early
        const float* Ab = As + (c & 1) * AS_SZ + (wr * 32 + lr) * AS_STRIDE;
        const ull* Wb = Wp + (c * 32) * WP_STRIDE + wc * 64 + lc;
#pragma unroll 2
        for (int kpl = 0; kpl < 32; kpl++) {
            ull a[8], w[8];
#pragma unroll
            for (int r = 0; r < 8; r++)
                a[r] = *reinterpret_cast<const ull*>(Ab + 4 * r * AS_STRIDE + 2 * kpl);
#pragma unroll
            for (int cc = 0; cc < 8; cc++)
                w[cc] = Wb[kpl * WP_STRIDE + 8 * cc];
#pragma unroll
            for (int r = 0; r < 8; r++)
#pragma unroll
                for (int cc = 0; cc < 8; cc++)
                    asm("fma.rn.f32x2 %0, %1, %2, %0;"
                        : "+l"(acc[r][cc]) : "l"(a[r]), "l"(w[cc]));
        }
        if (c < 3) {
            store_chunk((c + 1) & 1);
            __syncthreads();
        }
    }

    // ---- epilogue: combine even/odd partials, bias, relu, store
#pragma unroll
    for (int r = 0; r < 8; r++) {
        int row = row0 + wr * 32 + lr + 4 * r;
        if (row < NN) {
#pragma unroll
            for (int cc = 0; cc < 8; cc++) {
                int col = wc * 64 + lc + 8 * cc;
                float lo = __uint_as_float((unsigned)(acc[r][cc] & 0xffffffffull));
                float hi = __uint_as_float((unsigned)(acc[r][cc] >> 32));
                float v = lo + hi + bias[col];
                if (do_relu) v = fmaxf(v, 0.f);
                out[(size_t)row * DD + col] = v;
            }
        }
    }
}

extern "C" void kernel_launch(void* const* d_in, const int* in_sizes, int n_in,
                              void* d_out, int out_size) {
    const float* x   = (const float*)d_in[0];
    const void*  edg = d_in[1];
    const float* W1l = (const float*)d_in[2];
    const float* b1  = (const float*)d_in[3];
    const float* W1r = (const float*)d_in[4];
    const float* W2l = (const float*)d_in[5];
    const float* b2  = (const float*)d_in[6];
    const float* W2r = (const float*)d_in[7];
    float* out = (float*)d_out;

    cudaFuncSetAttribute(k_gemm, cudaFuncAttributeMaxDynamicSharedMemorySize, GSMEM);

    const int gemm_blocks = (NN + 127) / 128;        // 782
    const int scat_blocks = NE / 8;                   // warp per edge, 256 thr/blk

    k_detect<<<1, 32>>>((const unsigned int*)edg);

    // Layer 1
    k_zero<<<2048, 256>>>(1);
    k_scatter<<<scat_blocks, 256>>>(x, edg, /*with_deg=*/1, /*use_h=*/0);
    k_mean<<<2048, 256>>>();
    k_gemm<<<gemm_blocks, 256, GSMEM>>>(x, W1l, W1r, b1, out,
                                        /*use_h_in=*/0, /*use_h_out=*/1, /*relu=*/1);
    // Layer 2
    k_zero<<<2048, 256>>>(0);
    k_scatter<<<scat_blocks, 256>>>(x, edg, /*with_deg=*/0, /*use_h=*/1);
    k_mean<<<2048, 256>>>();
    k_gemm<<<gemm_blocks, 256, GSMEM>>>(x, W2l, W2r, b2, out,
                                        /*use_h_in=*/1, /*use_h_out=*/0, /*relu=*/0);
}

// round 3
// speedup vs baseline: 1.7027x; 1.5388x over previous
#include <cuda_runtime.h>
#include <cstdint>
typedef unsigned long long ull;

#define NN 100000
#define NE 1600000
#define DD 128
#define NB_SCAN 391            // 391*256 = 100096 >= NN

// -------- scratch (device globals: no allocation allowed) --------
__device__ __align__(256) float g_agg[(size_t)NN * DD];   // 51.2 MB (holds MEAN after gather)
__device__ __align__(256) float g_h[(size_t)NN * DD];     // 51.2 MB
__device__ int g_cnt[NN];
__device__ int g_incl[NN];
__device__ int g_rowp[NN + 1];
__device__ int g_cur[NN];
__device__ int g_adj[NE];
__device__ int g_bsum[NB_SCAN];
__device__ int g_boff[512];
__device__ int g_is64;

// -------- edge dtype detection: int64 -> odd 32-bit words are all 0 --------
__global__ void k_detect(const unsigned int* __restrict__ e) {
    int bad = 0;
    for (int i = threadIdx.x; i < 256; i += 32)
        if (e[2 * i + 1] != 0u) bad = 1;
    unsigned any = __ballot_sync(0xffffffffu, bad);
    if (threadIdx.x == 0) g_is64 = (any == 0u) ? 1 : 0;
}

__device__ __forceinline__ void edge_pair(const void* edge, int i, int& s, int& d) {
    if (g_is64) {
        const long long* e = (const long long*)edge;
        s = (int)e[i]; d = (int)e[NE + i];
    } else {
        const int* e = (const int*)edge;
        s = e[i]; d = e[NE + i];
    }
}

// -------- CSR build --------
__global__ void k_zero_cnt() {
    int i = blockIdx.x * blockDim.x + threadIdx.x;
    if (i < NN) g_cnt[i] = 0;
}

__global__ void k_hist(const void* __restrict__ edge) {
    int i = blockIdx.x * blockDim.x + threadIdx.x;
    if (i >= NE) return;
    int s, d; edge_pair(edge, i, s, d);
    atomicAdd(&g_cnt[d], 1);
}

__global__ void k_scan1() {
    __shared__ int sh[256];
    int tid = threadIdx.x;
    int i = blockIdx.x * 256 + tid;
    int v = (i < NN) ? g_cnt[i] : 0;
    sh[tid] = v;
    __syncthreads();
    for (int ofs = 1; ofs < 256; ofs <<= 1) {
        int t = (tid >= ofs) ? sh[tid - ofs] : 0;
        __syncthreads();
        sh[tid] += t;
        __syncthreads();
    }
    if (i < NN) g_incl[i] = sh[tid];
    if (tid == 255) g_bsum[blockIdx.x] = sh[255];
}

__global__ void k_scan2() {
    __shared__ int sh[512];
    int tid = threadIdx.x;
    int v = (tid < NB_SCAN) ? g_bsum[tid] : 0;
    sh[tid] = v;
    __syncthreads();
    for (int ofs = 1; ofs < 512; ofs <<= 1) {
        int t = (tid >= ofs) ? sh[tid - ofs] : 0;
        __syncthreads();
        sh[tid] += t;
        __syncthreads();
    }
    g_boff[tid] = sh[tid] - v;          // exclusive
}

__global__ void k_scan3() {
    int i = blockIdx.x * blockDim.x + threadIdx.x;
    if (i >= NN) return;
    int incl = g_incl[i] + g_boff[i >> 8];
    g_rowp[i + 1] = incl;
    g_cur[i] = incl - g_cnt[i];
    if (i == 0) g_rowp[0] = 0;
}

__global__ void k_fill(const void* __restrict__ edge) {
    int i = blockIdx.x * blockDim.x + threadIdx.x;
    if (i >= NE) return;
    int s, d; edge_pair(edge, i, s, d);
    int pos = atomicAdd(&g_cur[d], 1);
    g_adj[pos] = s;
}

// -------- gather: warp per node, mean written directly --------
__global__ __launch_bounds__(256)
void k_gather(const float* __restrict__ xext, int use_h) {
    const float4* __restrict__ X4 =
        reinterpret_cast<const float4*>(use_h ? g_h : xext);
    unsigned node = (blockIdx.x * blockDim.x + threadIdx.x) >> 5;
    int lane = threadIdx.x & 31;
    if (node >= NN) return;
    int beg = g_rowp[node], end = g_rowp[node + 1];
    float4 acc = make_float4(0.f, 0.f, 0.f, 0.f);
    for (int j0 = beg; j0 < end; j0 += 32) {
        int nb = min(32, end - j0);
        int src = (lane < nb) ? g_adj[j0 + lane] : 0;
#pragma unroll 4
        for (int t = 0; t < nb; t++) {
            int s = __shfl_sync(0xffffffffu, src, t);
            float4 v = X4[(size_t)s * 32 + lane];
            acc.x += v.x; acc.y += v.y; acc.z += v.z; acc.w += v.w;
        }
    }
    float inv = 1.0f / fmaxf((float)(end - beg), 1.0f);
    acc.x *= inv; acc.y *= inv; acc.z *= inv; acc.w *= inv;
    reinterpret_cast<float4*>(g_agg)[(size_t)node * 32 + lane] = acc;
}

// -------- fused SAGE layer GEMM (unchanged from R2; g_agg holds mean) --------
#define AS_STRIDE 68
#define AS_SZ (128 * AS_STRIDE)
#define WP_STRIDE 130
#define GSMEM (2 * AS_SZ * 4 + 128 * WP_STRIDE * 8)

__global__ __launch_bounds__(256, 1)
void k_gemm(const float* __restrict__ Xext,
            const float* __restrict__ Wl, const float* __restrict__ Wr,
            const float* __restrict__ bias,
            float* __restrict__ outext,
            int use_h_in, int use_h_out, int do_relu) {
    extern __shared__ float sm[];
    float* As = sm;
    ull* Wp = reinterpret_cast<ull*>(sm + 2 * AS_SZ);
    const float* __restrict__ X = use_h_in ? g_h : Xext;
    float* __restrict__ out = use_h_out ? g_h : outext;

    int tid = threadIdx.x;
    int row0 = blockIdx.x * 128;
    int wid = tid >> 5, lane = tid & 31;
    int wr = wid & 3, wc = wid >> 2;
    int lr = lane >> 3, lc = lane & 7;

    {
        const float2* w0 = (const float2*)Wl;
        const float2* w1 = (const float2*)Wr;
        for (int i = tid; i < 8192; i += 256) {
            int col = i >> 6, kpl = i & 63;
            float2 v0 = w0[col * 64 + kpl];
            float2 v1 = w1[col * 64 + kpl];
            Wp[kpl * WP_STRIDE + col] = *reinterpret_cast<ull*>(&v0);
            Wp[(kpl + 64) * WP_STRIDE + col] = *reinterpret_cast<ull*>(&v1);
        }
    }

    float4 ld[8];
    auto load_chunk = [&](int c) {
        const float* P = (c < 2) ? g_agg : X;
        int off = (c & 1) * 64;
#pragma unroll
        for (int j = 0; j < 8; j++) {
            int i = j * 256 + tid;
            int r = i >> 4, f4c = i & 15;
            int row = row0 + r;
            if (row < NN)
                ld[j] = *reinterpret_cast<const float4*>(P + (size_t)row * DD + off + f4c * 4);
            else
                ld[j] = make_float4(0.f, 0.f, 0.f, 0.f);
        }
    };
    auto store_chunk = [&](int b) {
#pragma unroll
        for (int j = 0; j < 8; j++) {
            int i = j * 256 + tid;
            int r = i >> 4, f4c = i & 15;
            *reinterpret_cast<float4*>(As + b * AS_SZ + r * AS_STRIDE + f4c * 4) = ld[j];
        }
    };

    ull acc[8][8];
#pragma unroll
    for (int r = 0; r < 8; r++)
#pragma unroll
        for (int c = 0; c < 8; c++) acc[r][c] = 0ull;

    load_chunk(0);
    store_chunk(0);
    __syncthreads();

    for (int c = 0; c < 4; c++) {
        if (c < 3) load_chunk(c + 1);
        const float* Ab = As + (c & 1) * AS_SZ + (wr * 32 + lr) * AS_STRIDE;
        const ull* Wb = Wp + (c * 32) * WP_STRIDE + wc * 64 + lc;
#pragma unroll 2
        for (int kpl = 0; kpl < 32; kpl++) {
            ull a[8], w[8];
#pragma unroll
            for (int r = 0; r < 8; r++)
                a[r] = *reinterpret_cast<const ull*>(Ab + 4 * r * AS_STRIDE + 2 * kpl);
#pragma unroll
            for (int cc = 0; cc < 8; cc++)
                w[cc] = Wb[kpl * WP_STRIDE + 8 * cc];
#pragma unroll
            for (int r = 0; r < 8; r++)
#pragma unroll
                for (int cc = 0; cc < 8; cc++)
                    asm("fma.rn.f32x2 %0, %1, %2, %0;"
                        : "+l"(acc[r][cc]) : "l"(a[r]), "l"(w[cc]));
        }
        if (c < 3) {
            store_chunk((c + 1) & 1);
            __syncthreads();
        }
    }

#pragma unroll
    for (int r = 0; r < 8; r++) {
        int row = row0 + wr * 32 + lr + 4 * r;
        if (row < NN) {
#pragma unroll
            for (int cc = 0; cc < 8; cc++) {
                int col = wc * 64 + lc + 8 * cc;
                float lo = __uint_as_float((unsigned)(acc[r][cc] & 0xffffffffull));
                float hi = __uint_as_float((unsigned)(acc[r][cc] >> 32));
                float v = lo + hi + bias[col];
                if (do_relu) v = fmaxf(v, 0.f);
                out[(size_t)row * DD + col] = v;
            }
        }
    }
}

extern "C" void kernel_launch(void* const* d_in, const int* in_sizes, int n_in,
                              void* d_out, int out_size) {
    const float* x   = (const float*)d_in[0];
    const void*  edg = d_in[1];
    const float* W1l = (const float*)d_in[2];
    const float* b1  = (const float*)d_in[3];
    const float* W1r = (const float*)d_in[4];
    const float* W2l = (const float*)d_in[5];
    const float* b2  = (const float*)d_in[6];
    const float* W2r = (const float*)d_in[7];
    float* out = (float*)d_out;

    cudaFuncSetAttribute(k_gemm, cudaFuncAttributeMaxDynamicSharedMemorySize, GSMEM);

    const int gemm_blocks = (NN + 127) / 128;        // 782
    const int edge_blocks = (NE + 255) / 256;        // 6250
    const int node_blocks = (NN + 255) / 256;        // 391
    const int gath_blocks = (NN * 32 + 255) / 256;   // 12500 (warp per node)

    k_detect<<<1, 32>>>((const unsigned int*)edg);

    // ---- CSR build (once, reused by both layers)
    k_zero_cnt<<<node_blocks, 256>>>();
    k_hist<<<edge_blocks, 256>>>(edg);
    k_scan1<<<NB_SCAN, 256>>>();
    k_scan2<<<1, 512>>>();
    k_scan3<<<node_blocks, 256>>>();
    k_fill<<<edge_blocks, 256>>>(edg);

    // ---- Layer 1
    k_gather<<<gath_blocks, 256>>>(x, /*use_h=*/0);
    k_gemm<<<gemm_blocks, 256, GSMEM>>>(x, W1l, W1r, b1, out,
                                        /*use_h_in=*/0, /*use_h_out=*/1, /*relu=*/1);
    // ---- Layer 2
    k_gather<<<gath_blocks, 256>>>(x, /*use_h=*/1);
    k_gemm<<<gemm_blocks, 256, GSMEM>>>(x, W2l, W2r, b2, out,
                                        /*use_h_in=*/1, /*use_h_out=*/0, /*relu=*/0);
}